// round 12
// baseline (speedup 1.0000x reference)
#include <cuda_runtime.h>
#include <cstdint>

// Gaussian 15x15 separable blur, 8192x8192 fp32, reflect pad, stride 1.
// Scanline streaming: cp.async 10-row groups (2 in flight) into a 20-row
// smem ring (21.8 KB -> 7 CTAs/SM). Horizontal conv 2 cols/thread with
// symmetric taps; vertical conv via 15-slot scalar accumulator ring.
// ALL Gaussian coefficients are compile-time fp32 immediates (sigma=3,
// ksize=15 fixed by the problem) -> FFMA-imm at rt=1, zero coeff registers.

#define IMG_W 8192
#define IMG_H 8192
#define KS 15
#define HALO 7
#define TPB 128
#define TILE_W 256
#define TILE_H 64
#define NROWS (TILE_H + 2*HALO)     // 78 input rows per strip
#define ROW_F 272                   // floats per buffered row (x0-8 .. x0+263)
#define ROW_P (ROW_F/2)             // 136 float2 per row
#define RING 20                     // 2 x 10-row groups
#define SMEM_BYTES (RING * ROW_F * 4)   // 21760 B -> 7 CTAs/SM

// Normalized 1D Gaussian taps, sigma=3, 15 taps (computed in double):
// KC[i] = coefficient at distance (7-i) from center; KC[7] = center.
__device__ __constant__ const float KCC[8] = {0};   // (unused; immediates below)
#define KC0 0.00884695f   // dist 7
#define KC1 0.01821591f   // dist 6
#define KC2 0.03356239f   // dist 5
#define KC3 0.05533506f   // dist 4
#define KC4 0.08163801f   // dist 3
#define KC5 0.10777792f   // dist 2
#define KC6 0.12732457f   // dist 1
#define KC7 0.13459834f   // center

__device__ __forceinline__ int reflect_idx(int p, int n) {
    p = (p < 0) ? -p : p;
    p = (p >= n) ? (2*n - 2 - p) : p;
    return p;
}
__device__ __forceinline__ void cp16(uint32_t saddr, const float* g) {
    asm volatile("cp.async.cg.shared.global [%0], [%1], 16;"
                 :: "r"(saddr), "l"(g) : "memory");
}
#define CP_COMMIT() asm volatile("cp.async.commit_group;" ::: "memory")
#define CP_WAIT(N)  asm volatile("cp.async.wait_group %0;" :: "n"(N) : "memory")

// Coefficient by symmetric kernel index ci = min(d, 14-d), compile-time.
template<int CI> __device__ __forceinline__ float kc() {
    return (CI == 0) ? KC0 : (CI == 1) ? KC1 : (CI == 2) ? KC2 :
           (CI == 3) ? KC3 : (CI == 4) ? KC4 : (CI == 5) ? KC5 :
           (CI == 6) ? KC6 : KC7;
}

// One input row in ring slot SLOT (compile-time), AMOD = r mod 15:
// horizontal 15-tap conv for this thread's 2 cols (symmetric, FFMA-imm),
// vertical accumulate into 15-slot scalar ring; optionally emit row r-14.
template<int SLOT, int AMOD, int DMAX, bool EMIT>
__device__ __forceinline__ void rstep(const float2* __restrict__ wb,
                                      float* acc, float* op) {
    const float2* w = wb + SLOT * ROW_P;    // immediate offset
    float f[18];
#pragma unroll
    for (int c = 0; c < 9; c++) {
        float2 v = w[c];
        f[2*c] = v.x; f[2*c+1] = v.y;
    }
    // col0 (= x0+2t): taps f[1..15]; col1: taps f[2..16]
    float s0 = f[1]+f[15], s1 = f[2]+f[14], s2 = f[3]+f[13], s3 = f[4]+f[12],
          s4 = f[5]+f[11], s5 = f[6]+f[10], s6 = f[7]+f[9];
    float h0 = (fmaf(s1, KC1, s0 * KC0) + fmaf(s3, KC3, s2 * KC2))
             + (fmaf(s5, KC5, s4 * KC4) + fmaf(f[8], KC7, s6 * KC6));
    float u0 = f[2]+f[16], u1 = f[3]+f[15], u2 = f[4]+f[14], u3 = f[5]+f[13],
          u4 = f[6]+f[12], u5 = f[7]+f[11], u6 = f[8]+f[10];
    float h1 = (fmaf(u1, KC1, u0 * KC0) + fmaf(u3, KC3, u2 * KC2))
             + (fmaf(u5, KC5, u4 * KC4) + fmaf(f[9], KC7, u6 * KC6));

    // vertical: row r feeds outputs t = r-d, d = 0..DMAX, coeff k[min(d,14-d)]
#pragma unroll
    for (int d = 0; d <= DMAX; d++) {
        const int s = ((AMOD - d) % 15 + 15) % 15;
        const int ci = (d < 8) ? d : 14 - d;
        const float k = (ci==0)?KC0:(ci==1)?KC1:(ci==2)?KC2:(ci==3)?KC3:
                        (ci==4)?KC4:(ci==5)?KC5:(ci==6)?KC6:KC7;
        acc[2*s]   = fmaf(h0, k, acc[2*s]);
        acc[2*s+1] = fmaf(h1, k, acc[2*s+1]);
    }
    if (EMIT) {
        constexpr int st = (AMOD + 1) % 15;   // slot of output row r-14
        *(float2*)op = make_float2(acc[2*st], acc[2*st+1]);
        acc[2*st] = 0.f; acc[2*st+1] = 0.f;
    }
}

// Async prefetch of up to 10 rows [base, base+10) into ring slots
// sbase..sbase+9. Warp w handles rows w, w+4, ... (division-free). Commits.
__device__ __forceinline__ void prefetch10(uint32_t ring_s, float* ring_g,
                                           const float* in, int x0, int y0,
                                           int base, int sbase,
                                           bool xb, int tid) {
    if (base < NROWS) {
        int nr = NROWS - base; if (nr > 10) nr = 10;
        const int wrp = tid >> 5, lane = tid & 31;
        if (!xb) {
#pragma unroll 1
            for (int rr = wrp; rr < nr; rr += 4) {
                int gy = reflect_idx(y0 - HALO + base + rr, IMG_H);
                const float* src = in + (size_t)gy * IMG_W + (x0 - 8);
                uint32_t dst = ring_s + (uint32_t)((sbase + rr) * ROW_F * 4);
                cp16(dst + lane * 16,        src + lane * 4);
                cp16(dst + (lane + 32) * 16, src + (lane + 32) * 4);
                if (lane < 4)
                    cp16(dst + (lane + 64) * 16, src + (lane + 64) * 4);
            }
        } else {
#pragma unroll 1
            for (int rr = wrp; rr < nr; rr += 4) {
                int gy = reflect_idx(y0 - HALO + base + rr, IMG_H);
                const float* row = in + (size_t)gy * IMG_W;
                float* dst = ring_g + (sbase + rr) * ROW_F;
                for (int i = lane; i < ROW_F; i += 32)
                    dst[i] = __ldg(row + reflect_idx(x0 - 8 + i, IMG_W));
            }
        }
    }
    CP_COMMIT();
}

extern __shared__ float ring[];

__global__ void __launch_bounds__(TPB, 7)
gauss_kernel(const float* __restrict__ in, float* __restrict__ out) {
    const int tid = threadIdx.x;
    const int x0 = blockIdx.x * TILE_W;
    const int y0 = blockIdx.y * TILE_H;
    const bool xb = (blockIdx.x == 0) || (blockIdx.x == gridDim.x - 1);
    const uint32_t ring_s = (uint32_t)__cvta_generic_to_shared(ring);
    const float2* wb = (const float2*)ring + tid;    // thread's first tap pair

    float acc[30];
#pragma unroll
    for (int i = 0; i < 30; i++) acc[i] = 0.f;

    float* outx = out + (size_t)y0 * IMG_W + x0 + 2 * tid;
    const size_t W = IMG_W;

    // Prime: g0 (rows 0-9 -> slots 0-9), g1 (rows 10-19 -> slots 10-19).
    prefetch10(ring_s, ring, in, x0, y0,  0,  0, xb, tid);
    prefetch10(ring_s, ring, in, x0, y0, 10, 10, xb, tid);

    // Block b: wait g_b done; sync; compute its 10 rows; sync (slots of g_b
    // now reusable); prefetch g_{b+2} into the same slot half; commit.
#define BTOP() CP_WAIT(1); __syncthreads();
#define BEND(BASE, SB) __syncthreads(); \
    prefetch10(ring_s, ring, in, x0, y0, (BASE), (SB), xb, tid);

    // Steady 10-row phases (slot base SB; amod sequences 0.., 10.., 5..)
#define PH_AM0(SB, ob) \
    rstep<(SB)+0, 0,14,true>(wb, acc, (ob) + 0*W); \
    rstep<(SB)+1, 1,14,true>(wb, acc, (ob) + 1*W); \
    rstep<(SB)+2, 2,14,true>(wb, acc, (ob) + 2*W); \
    rstep<(SB)+3, 3,14,true>(wb, acc, (ob) + 3*W); \
    rstep<(SB)+4, 4,14,true>(wb, acc, (ob) + 4*W); \
    rstep<(SB)+5, 5,14,true>(wb, acc, (ob) + 5*W); \
    rstep<(SB)+6, 6,14,true>(wb, acc, (ob) + 6*W); \
    rstep<(SB)+7, 7,14,true>(wb, acc, (ob) + 7*W); \
    rstep<(SB)+8, 8,14,true>(wb, acc, (ob) + 8*W); \
    rstep<(SB)+9, 9,14,true>(wb, acc, (ob) + 9*W);

#define PH_AM10(SB, ob) \
    rstep<(SB)+0,10,14,true>(wb, acc, (ob) + 0*W); \
    rstep<(SB)+1,11,14,true>(wb, acc, (ob) + 1*W); \
    rstep<(SB)+2,12,14,true>(wb, acc, (ob) + 2*W); \
    rstep<(SB)+3,13,14,true>(wb, acc, (ob) + 3*W); \
    rstep<(SB)+4,14,14,true>(wb, acc, (ob) + 4*W); \
    rstep<(SB)+5, 0,14,true>(wb, acc, (ob) + 5*W); \
    rstep<(SB)+6, 1,14,true>(wb, acc, (ob) + 6*W); \
    rstep<(SB)+7, 2,14,true>(wb, acc, (ob) + 7*W); \
    rstep<(SB)+8, 3,14,true>(wb, acc, (ob) + 8*W); \
    rstep<(SB)+9, 4,14,true>(wb, acc, (ob) + 9*W);

#define PH_AM5(SB, ob) \
    rstep<(SB)+0, 5,14,true>(wb, acc, (ob) + 0*W); \
    rstep<(SB)+1, 6,14,true>(wb, acc, (ob) + 1*W); \
    rstep<(SB)+2, 7,14,true>(wb, acc, (ob) + 2*W); \
    rstep<(SB)+3, 8,14,true>(wb, acc, (ob) + 3*W); \
    rstep<(SB)+4, 9,14,true>(wb, acc, (ob) + 4*W); \
    rstep<(SB)+5,10,14,true>(wb, acc, (ob) + 5*W); \
    rstep<(SB)+6,11,14,true>(wb, acc, (ob) + 6*W); \
    rstep<(SB)+7,12,14,true>(wb, acc, (ob) + 7*W); \
    rstep<(SB)+8,13,14,true>(wb, acc, (ob) + 8*W); \
    rstep<(SB)+9,14,14,true>(wb, acc, (ob) + 9*W);

    // ---- B0: rows 0..9 (warmup) ----
    BTOP()
    rstep<0,0,0,false>(wb, acc, outx);
    rstep<1,1,1,false>(wb, acc, outx);
    rstep<2,2,2,false>(wb, acc, outx);
    rstep<3,3,3,false>(wb, acc, outx);
    rstep<4,4,4,false>(wb, acc, outx);
    rstep<5,5,5,false>(wb, acc, outx);
    rstep<6,6,6,false>(wb, acc, outx);
    rstep<7,7,7,false>(wb, acc, outx);
    rstep<8,8,8,false>(wb, acc, outx);
    rstep<9,9,9,false>(wb, acc, outx);
    BEND(20, 0)                                     // g2: rows 20-29 -> slots 0-9

    // ---- B1: rows 10..19 (rows 14..19 emit outputs 0..5) ----
    BTOP()
    rstep<10,10,10,false>(wb, acc, outx);
    rstep<11,11,11,false>(wb, acc, outx);
    rstep<12,12,12,false>(wb, acc, outx);
    rstep<13,13,13,false>(wb, acc, outx);
    rstep<14,14,14,true >(wb, acc, outx + 0*W);
    rstep<15, 0,14,true >(wb, acc, outx + 1*W);
    rstep<16, 1,14,true >(wb, acc, outx + 2*W);
    rstep<17, 2,14,true >(wb, acc, outx + 3*W);
    rstep<18, 3,14,true >(wb, acc, outx + 4*W);
    rstep<19, 4,14,true >(wb, acc, outx + 5*W);
    BEND(30, 10)                                    // g3: rows 30-39 -> slots 10-19

    // ---- B2: rows 20..29 -> outputs 6..15 ----
    BTOP()
    PH_AM5(0, outx + (size_t)6 * W)
    BEND(40, 0)                                     // g4
    // ---- B3: rows 30..39 -> outputs 16..25 ----
    BTOP()
    PH_AM0(10, outx + (size_t)16 * W)
    BEND(50, 10)                                    // g5
    // ---- B4: rows 40..49 -> outputs 26..35 ----
    BTOP()
    PH_AM10(0, outx + (size_t)26 * W)
    BEND(60, 0)                                     // g6
    // ---- B5: rows 50..59 -> outputs 36..45 ----
    BTOP()
    PH_AM5(10, outx + (size_t)36 * W)
    BEND(70, 10)                                    // g7: rows 70-77 -> slots 10-17
    // ---- B6: rows 60..69 -> outputs 46..55 ----
    BTOP()
    PH_AM0(0, outx + (size_t)46 * W)
    BEND(80, 0)                                     // g8: empty commit
    // ---- B7: rows 70..77 -> outputs 56..63 ----
    BTOP()
    {
        float* ob = outx + (size_t)56 * W;
        rstep<10,10,14,true>(wb, acc, ob + 0*W);
        rstep<11,11,14,true>(wb, acc, ob + 1*W);
        rstep<12,12,14,true>(wb, acc, ob + 2*W);
        rstep<13,13,14,true>(wb, acc, ob + 3*W);
        rstep<14,14,14,true>(wb, acc, ob + 4*W);
        rstep<15, 0,14,true>(wb, acc, ob + 5*W);
        rstep<16, 1,14,true>(wb, acc, ob + 6*W);
        rstep<17, 2,14,true>(wb, acc, ob + 7*W);
    }
}

extern "C" void kernel_launch(void* const* d_in, const int* in_sizes, int n_in,
                              void* d_out, int out_size) {
    const float* img = (const float*)d_in[0];   // [8192,8192] f32
    float* out = (float*)d_out;                 // [8192,8192] f32
    (void)in_sizes; (void)n_in; (void)out_size; (void)d_in;

    dim3 grid(IMG_W / TILE_W, IMG_H / TILE_H);  // 32 x 128
    gauss_kernel<<<grid, TPB, SMEM_BYTES>>>(img, out);
}

// round 13
// speedup vs baseline: 1.1555x; 1.1555x over previous
#include <cuda_runtime.h>
#include <cstdint>

// Gaussian 15x15 separable blur, 8192x8192 fp32, reflect pad, stride 1.
// R12 = R10 packed-hybrid compute body + R11 7-CTA schedule:
//   - cp.async 10-row groups (2 in flight) into a 20-row smem ring (21.8 KB)
//   - horizontal conv 2 cols/thread: packed-odd taps (f32x2 regs) +
//     scalar-even taps with IMMEDIATE coefficients (FFMA-imm, rt=1)
//   - vertical conv: 15-slot packed f32x2 accumulator ring, 8 packed coeff regs
//   - all coefficients compile-time (sigma=3, ksize=15 fixed); no prep kernel
// All smem-slot / acc-slot indices are compile-time immediates.

#define IMG_W 8192
#define IMG_H 8192
#define HALO 7
#define TPB 128
#define TILE_W 256
#define TILE_H 64
#define NROWS (TILE_H + 2*HALO)     // 78 input rows per strip
#define ROW_F 272                   // floats per buffered row (x0-8 .. x0+263)
#define ROW_U (ROW_F/2)             // 136 ull per row
#define RING 20                     // 2 x 10-row groups
#define SMEM_BYTES (RING * ROW_F * 4)   // 21760 B -> 7 CTAs/SM

// Normalized 1D Gaussian taps, sigma=3, 15 taps (double-precision derived).
// KCi = coefficient at kernel index i (distance 7-i from center); KC7 = center.
#define KC0 0.00884695f
#define KC1 0.01821591f
#define KC2 0.03356239f
#define KC3 0.05533506f
#define KC4 0.08163801f
#define KC5 0.10777792f
#define KC6 0.12732457f
#define KC7 0.13459834f

typedef unsigned long long ull;

__device__ __forceinline__ int reflect_idx(int p, int n) {
    p = (p < 0) ? -p : p;
    p = (p >= n) ? (2*n - 2 - p) : p;
    return p;
}
__device__ __forceinline__ ull pk2(float lo, float hi) {
    ull r; asm("mov.b64 %0, {%1, %2};" : "=l"(r) : "f"(lo), "f"(hi)); return r;
}
__device__ __forceinline__ void upk2(ull v, float& lo, float& hi) {
    asm("mov.b64 {%0, %1}, %2;" : "=f"(lo), "=f"(hi) : "l"(v));
}
__device__ __forceinline__ ull ffma2(ull a, ull b, ull c) {
    ull d; asm("fma.rn.f32x2 %0, %1, %2, %3;" : "=l"(d) : "l"(a), "l"(b), "l"(c)); return d;
}
__device__ __forceinline__ ull add2(ull a, ull b) {
    ull d; asm("add.rn.f32x2 %0, %1, %2;" : "=l"(d) : "l"(a), "l"(b)); return d;
}
__device__ __forceinline__ ull mul2(ull a, ull b) {
    ull d; asm("mul.rn.f32x2 %0, %1, %2;" : "=l"(d) : "l"(a), "l"(b)); return d;
}
__device__ __forceinline__ void cp16(uint32_t saddr, const float* g) {
    asm volatile("cp.async.cg.shared.global [%0], [%1], 16;"
                 :: "r"(saddr), "l"(g) : "memory");
}
#define CP_COMMIT() asm volatile("cp.async.commit_group;" ::: "memory")
#define CP_WAIT(N)  asm volatile("cp.async.wait_group %0;" :: "n"(N) : "memory")

// One input row in ring slot SLOT (compile-time), AMOD = r mod 15:
// horizontal conv for this thread's 2 cols, vertical accumulate into the
// 15-slot packed acc ring; optionally emit output row r-14.
//   odd taps : packed f32x2 on aligned smem pairs (symmetric, 4 packed coeffs)
//   even taps: scalar symmetric sums with IMMEDIATE coefficients (FFMA-imm)
template<int SLOT, int AMOD, int DMAX, bool EMIT>
__device__ __forceinline__ void rstep(const ull* __restrict__ wb,
                                      ull* acc, const ull* k2, float* op) {
    const ull* w = wb + SLOT * ROW_U;       // immediate offset
    ull P0 = w[0], P1 = w[1], P2 = w[2], P3 = w[3], P4 = w[4],
        P5 = w[5], P6 = w[6], P7 = w[7], P8 = w[8];
    float lo0, hi0, lo1, hi1, lo2, hi2, lo3, hi3, lo4, hi4,
          lo5, hi5, lo6, hi6, lo7, hi7, lo8, hi8;
    upk2(P0, lo0, hi0); upk2(P1, lo1, hi1); upk2(P2, lo2, hi2);
    upk2(P3, lo3, hi3); upk2(P4, lo4, hi4); upk2(P5, lo5, hi5);
    upk2(P6, lo6, hi6); upk2(P7, lo7, hi7); upk2(P8, lo8, hi8);

    // packed odd taps (j=1..13 odd -> coeffs KC1,KC3,KC5,KC7 via symmetry)
    ull s1 = add2(P1, P7);
    ull s2 = add2(P2, P6);
    ull s3 = add2(P3, P5);
    ull c1 = ffma2(k2[3], s2, mul2(k2[1], s1));
    ull c2 = ffma2(k2[5], s3, mul2(k2[7], P4));
    ull hod = add2(c1, c2);

    // scalar even taps (j=0..14 even -> KC0,KC2,KC4,KC6) with immediates
    float t0 = hi0 + hi7, t1 = hi1 + hi6, t2 = hi2 + hi5, t3 = hi3 + hi4;
    float e0 = fmaf(t1, KC2, t0 * KC0) + fmaf(t3, KC6, t2 * KC4);
    float u0 = lo1 + lo8, u1 = lo2 + lo7, u2 = lo3 + lo6, u3 = lo4 + lo5;
    float e1 = fmaf(u1, KC2, u0 * KC0) + fmaf(u3, KC6, u2 * KC4);

    ull h = add2(hod, pk2(e0, e1));

    // vertical: row r feeds outputs t = r-d, d = 0..DMAX, coeff KC[min(d,14-d)]
#pragma unroll
    for (int d = 0; d <= DMAX; d++) {
        const int s = ((AMOD - d) % 15 + 15) % 15;
        const int ci = (d < 8) ? d : 14 - d;
        acc[s] = ffma2(k2[ci], h, acc[s]);
    }
    if (EMIT) {
        constexpr int st = (AMOD + 1) % 15;     // slot of output row r-14
        float o0, o1; upk2(acc[st], o0, o1);
        *(float2*)op = make_float2(o0, o1);
        acc[st] = 0ull;
    }
}

// Async prefetch of up to 10 rows [base, base+10) into ring slots
// sbase..sbase+9. Warp w handles rows w, w+4, ... (division-free). Commits.
__device__ __forceinline__ void prefetch10(uint32_t ring_s, float* ring_g,
                                           const float* in, int x0, int y0,
                                           int base, int sbase,
                                           bool xb, int tid) {
    if (base < NROWS) {
        int nr = NROWS - base; if (nr > 10) nr = 10;
        const int wrp = tid >> 5, lane = tid & 31;
        if (!xb) {
#pragma unroll 1
            for (int rr = wrp; rr < nr; rr += 4) {
                int gy = reflect_idx(y0 - HALO + base + rr, IMG_H);
                const float* src = in + (size_t)gy * IMG_W + (x0 - 8);
                uint32_t dst = ring_s + (uint32_t)((sbase + rr) * ROW_F * 4);
                cp16(dst + lane * 16,        src + lane * 4);
                cp16(dst + (lane + 32) * 16, src + (lane + 32) * 4);
                if (lane < 4)
                    cp16(dst + (lane + 64) * 16, src + (lane + 64) * 4);
            }
        } else {
#pragma unroll 1
            for (int rr = wrp; rr < nr; rr += 4) {
                int gy = reflect_idx(y0 - HALO + base + rr, IMG_H);
                const float* row = in + (size_t)gy * IMG_W;
                float* dst = ring_g + (sbase + rr) * ROW_F;
                for (int i = lane; i < ROW_F; i += 32)
                    dst[i] = __ldg(row + reflect_idx(x0 - 8 + i, IMG_W));
            }
        }
    }
    CP_COMMIT();
}

extern __shared__ float ring[];

__global__ void __launch_bounds__(TPB, 7)
gauss_kernel(const float* __restrict__ in, float* __restrict__ out) {
    const int tid = threadIdx.x;
    const int x0 = blockIdx.x * TILE_W;
    const int y0 = blockIdx.y * TILE_H;
    const bool xb = (blockIdx.x == 0) || (blockIdx.x == gridDim.x - 1);
    const uint32_t ring_s = (uint32_t)__cvta_generic_to_shared(ring);
    const ull* wb = (const ull*)ring + tid;          // thread's first tap pair

    // 8 packed coefficient registers (vertical + packed-odd horizontal).
    ull k2[8];
    k2[0] = pk2(KC0, KC0); k2[1] = pk2(KC1, KC1);
    k2[2] = pk2(KC2, KC2); k2[3] = pk2(KC3, KC3);
    k2[4] = pk2(KC4, KC4); k2[5] = pk2(KC5, KC5);
    k2[6] = pk2(KC6, KC6); k2[7] = pk2(KC7, KC7);

    ull acc[15];
#pragma unroll
    for (int i = 0; i < 15; i++) acc[i] = 0ull;

    float* outx = out + (size_t)y0 * IMG_W + x0 + 2 * tid;
    const size_t W = IMG_W;

    // Prime: g0 (rows 0-9 -> slots 0-9), g1 (rows 10-19 -> slots 10-19).
    prefetch10(ring_s, ring, in, x0, y0,  0,  0, xb, tid);
    prefetch10(ring_s, ring, in, x0, y0, 10, 10, xb, tid);

    // Block b: wait g_b done; sync; compute its 10 rows; sync (slots of g_b
    // now reusable); prefetch g_{b+2} into the same slot half; commit.
#define BTOP() CP_WAIT(1); __syncthreads();
#define BEND(BASE, SB) __syncthreads(); \
    prefetch10(ring_s, ring, in, x0, y0, (BASE), (SB), xb, tid);

    // Steady 10-row phases (slot base SB; amod sequences 0.., 10.., 5..)
#define PH_AM0(SB, ob) \
    rstep<(SB)+0, 0,14,true>(wb, acc, k2, (ob) + 0*W); \
    rstep<(SB)+1, 1,14,true>(wb, acc, k2, (ob) + 1*W); \
    rstep<(SB)+2, 2,14,true>(wb, acc, k2, (ob) + 2*W); \
    rstep<(SB)+3, 3,14,true>(wb, acc, k2, (ob) + 3*W); \
    rstep<(SB)+4, 4,14,true>(wb, acc, k2, (ob) + 4*W); \
    rstep<(SB)+5, 5,14,true>(wb, acc, k2, (ob) + 5*W); \
    rstep<(SB)+6, 6,14,true>(wb, acc, k2, (ob) + 6*W); \
    rstep<(SB)+7, 7,14,true>(wb, acc, k2, (ob) + 7*W); \
    rstep<(SB)+8, 8,14,true>(wb, acc, k2, (ob) + 8*W); \
    rstep<(SB)+9, 9,14,true>(wb, acc, k2, (ob) + 9*W);

#define PH_AM10(SB, ob) \
    rstep<(SB)+0,10,14,true>(wb, acc, k2, (ob) + 0*W); \
    rstep<(SB)+1,11,14,true>(wb, acc, k2, (ob) + 1*W); \
    rstep<(SB)+2,12,14,true>(wb, acc, k2, (ob) + 2*W); \
    rstep<(SB)+3,13,14,true>(wb, acc, k2, (ob) + 3*W); \
    rstep<(SB)+4,14,14,true>(wb, acc, k2, (ob) + 4*W); \
    rstep<(SB)+5, 0,14,true>(wb, acc, k2, (ob) + 5*W); \
    rstep<(SB)+6, 1,14,true>(wb, acc, k2, (ob) + 6*W); \
    rstep<(SB)+7, 2,14,true>(wb, acc, k2, (ob) + 7*W); \
    rstep<(SB)+8, 3,14,true>(wb, acc, k2, (ob) + 8*W); \
    rstep<(SB)+9, 4,14,true>(wb, acc, k2, (ob) + 9*W);

#define PH_AM5(SB, ob) \
    rstep<(SB)+0, 5,14,true>(wb, acc, k2, (ob) + 0*W); \
    rstep<(SB)+1, 6,14,true>(wb, acc, k2, (ob) + 1*W); \
    rstep<(SB)+2, 7,14,true>(wb, acc, k2, (ob) + 2*W); \
    rstep<(SB)+3, 8,14,true>(wb, acc, k2, (ob) + 3*W); \
    rstep<(SB)+4, 9,14,true>(wb, acc, k2, (ob) + 4*W); \
    rstep<(SB)+5,10,14,true>(wb, acc, k2, (ob) + 5*W); \
    rstep<(SB)+6,11,14,true>(wb, acc, k2, (ob) + 6*W); \
    rstep<(SB)+7,12,14,true>(wb, acc, k2, (ob) + 7*W); \
    rstep<(SB)+8,13,14,true>(wb, acc, k2, (ob) + 8*W); \
    rstep<(SB)+9,14,14,true>(wb, acc, k2, (ob) + 9*W);

    // ---- B0: rows 0..9 (warmup) ----
    BTOP()
    rstep<0,0,0,false>(wb, acc, k2, outx);
    rstep<1,1,1,false>(wb, acc, k2, outx);
    rstep<2,2,2,false>(wb, acc, k2, outx);
    rstep<3,3,3,false>(wb, acc, k2, outx);
    rstep<4,4,4,false>(wb, acc, k2, outx);
    rstep<5,5,5,false>(wb, acc, k2, outx);
    rstep<6,6,6,false>(wb, acc, k2, outx);
    rstep<7,7,7,false>(wb, acc, k2, outx);
    rstep<8,8,8,false>(wb, acc, k2, outx);
    rstep<9,9,9,false>(wb, acc, k2, outx);
    BEND(20, 0)                                     // g2: rows 20-29 -> slots 0-9

    // ---- B1: rows 10..19 (rows 14..19 emit outputs 0..5) ----
    BTOP()
    rstep<10,10,10,false>(wb, acc, k2, outx);
    rstep<11,11,11,false>(wb, acc, k2, outx);
    rstep<12,12,12,false>(wb, acc, k2, outx);
    rstep<13,13,13,false>(wb, acc, k2, outx);
    rstep<14,14,14,true >(wb, acc, k2, outx + 0*W);
    rstep<15, 0,14,true >(wb, acc, k2, outx + 1*W);
    rstep<16, 1,14,true >(wb, acc, k2, outx + 2*W);
    rstep<17, 2,14,true >(wb, acc, k2, outx + 3*W);
    rstep<18, 3,14,true >(wb, acc, k2, outx + 4*W);
    rstep<19, 4,14,true >(wb, acc, k2, outx + 5*W);
    BEND(30, 10)                                    // g3: rows 30-39 -> slots 10-19

    // ---- B2: rows 20..29 -> outputs 6..15 ----
    BTOP()
    PH_AM5(0, outx + (size_t)6 * W)
    BEND(40, 0)                                     // g4
    // ---- B3: rows 30..39 -> outputs 16..25 ----
    BTOP()
    PH_AM0(10, outx + (size_t)16 * W)
    BEND(50, 10)                                    // g5
    // ---- B4: rows 40..49 -> outputs 26..35 ----
    BTOP()
    PH_AM10(0, outx + (size_t)26 * W)
    BEND(60, 0)                                     // g6
    // ---- B5: rows 50..59 -> outputs 36..45 ----
    BTOP()
    PH_AM5(10, outx + (size_t)36 * W)
    BEND(70, 10)                                    // g7: rows 70-77 -> slots 10-17
    // ---- B6: rows 60..69 -> outputs 46..55 ----
    BTOP()
    PH_AM0(0, outx + (size_t)46 * W)
    BEND(80, 0)                                     // g8: empty commit
    // ---- B7: rows 70..77 -> outputs 56..63 ----
    BTOP()
    {
        float* ob = outx + (size_t)56 * W;
        rstep<10,10,14,true>(wb, acc, k2, ob + 0*W);
        rstep<11,11,14,true>(wb, acc, k2, ob + 1*W);
        rstep<12,12,14,true>(wb, acc, k2, ob + 2*W);
        rstep<13,13,14,true>(wb, acc, k2, ob + 3*W);
        rstep<14,14,14,true>(wb, acc, k2, ob + 4*W);
        rstep<15, 0,14,true>(wb, acc, k2, ob + 5*W);
        rstep<16, 1,14,true>(wb, acc, k2, ob + 6*W);
        rstep<17, 2,14,true>(wb, acc, k2, ob + 7*W);
    }
}

extern "C" void kernel_launch(void* const* d_in, const int* in_sizes, int n_in,
                              void* d_out, int out_size) {
    const float* img = (const float*)d_in[0];   // [8192,8192] f32
    float* out = (float*)d_out;                 // [8192,8192] f32
    (void)in_sizes; (void)n_in; (void)out_size;

    dim3 grid(IMG_W / TILE_W, IMG_H / TILE_H);  // 32 x 128
    gauss_kernel<<<grid, TPB, SMEM_BYTES>>>(img, out);
}

// round 14
// speedup vs baseline: 1.1667x; 1.0097x over previous
#include <cuda_runtime.h>
#include <cstdint>

// Gaussian 15x15 separable blur, 8192x8192 fp32, reflect pad, stride 1.
// R13 = R12 + __launch_bounds__(128, 8): force 64 regs/thread so 8 CTAs/SM
// fit the register file (65536/(128*8) = 64). The marginal registers are the
// immediate-built packed coefficients, which ptxas can rematerialize (MOV32I)
// instead of spilling.
//   - cp.async 10-row groups (2 in flight) into a 20-row smem ring (21.8 KB)
//   - horizontal conv 2 cols/thread: packed-odd taps (f32x2) +
//     scalar-even taps with IMMEDIATE coefficients (FFMA-imm, rt=1)
//   - vertical conv: 15-slot packed f32x2 accumulator ring
//   - all coefficients compile-time (sigma=3, ksize=15 fixed); no prep kernel
// All smem-slot / acc-slot indices are compile-time immediates.

#define IMG_W 8192
#define IMG_H 8192
#define HALO 7
#define TPB 128
#define TILE_W 256
#define TILE_H 64
#define NROWS (TILE_H + 2*HALO)     // 78 input rows per strip
#define ROW_F 272                   // floats per buffered row (x0-8 .. x0+263)
#define ROW_U (ROW_F/2)             // 136 ull per row
#define RING 20                     // 2 x 10-row groups
#define SMEM_BYTES (RING * ROW_F * 4)   // 21760 B -> 8 CTAs/SM (smem-wise)

// Normalized 1D Gaussian taps, sigma=3, 15 taps (double-precision derived).
// KCi = coefficient at kernel index i (distance 7-i from center); KC7 = center.
#define KC0 0.00884695f
#define KC1 0.01821591f
#define KC2 0.03356239f
#define KC3 0.05533506f
#define KC4 0.08163801f
#define KC5 0.10777792f
#define KC6 0.12732457f
#define KC7 0.13459834f

typedef unsigned long long ull;

__device__ __forceinline__ int reflect_idx(int p, int n) {
    p = (p < 0) ? -p : p;
    p = (p >= n) ? (2*n - 2 - p) : p;
    return p;
}
__device__ __forceinline__ ull pk2(float lo, float hi) {
    ull r; asm("mov.b64 %0, {%1, %2};" : "=l"(r) : "f"(lo), "f"(hi)); return r;
}
__device__ __forceinline__ void upk2(ull v, float& lo, float& hi) {
    asm("mov.b64 {%0, %1}, %2;" : "=f"(lo), "=f"(hi) : "l"(v));
}
__device__ __forceinline__ ull ffma2(ull a, ull b, ull c) {
    ull d; asm("fma.rn.f32x2 %0, %1, %2, %3;" : "=l"(d) : "l"(a), "l"(b), "l"(c)); return d;
}
__device__ __forceinline__ ull add2(ull a, ull b) {
    ull d; asm("add.rn.f32x2 %0, %1, %2;" : "=l"(d) : "l"(a), "l"(b)); return d;
}
__device__ __forceinline__ ull mul2(ull a, ull b) {
    ull d; asm("mul.rn.f32x2 %0, %1, %2;" : "=l"(d) : "l"(a), "l"(b)); return d;
}
__device__ __forceinline__ void cp16(uint32_t saddr, const float* g) {
    asm volatile("cp.async.cg.shared.global [%0], [%1], 16;"
                 :: "r"(saddr), "l"(g) : "memory");
}
#define CP_COMMIT() asm volatile("cp.async.commit_group;" ::: "memory")
#define CP_WAIT(N)  asm volatile("cp.async.wait_group %0;" :: "n"(N) : "memory")

// One input row in ring slot SLOT (compile-time), AMOD = r mod 15:
// horizontal conv for this thread's 2 cols, vertical accumulate into the
// 15-slot packed acc ring; optionally emit output row r-14.
template<int SLOT, int AMOD, int DMAX, bool EMIT>
__device__ __forceinline__ void rstep(const ull* __restrict__ wb,
                                      ull* acc, const ull* k2, float* op) {
    const ull* w = wb + SLOT * ROW_U;       // immediate offset
    ull P0 = w[0], P1 = w[1], P2 = w[2], P3 = w[3], P4 = w[4],
        P5 = w[5], P6 = w[6], P7 = w[7], P8 = w[8];
    float lo0, hi0, lo1, hi1, lo2, hi2, lo3, hi3, lo4, hi4,
          lo5, hi5, lo6, hi6, lo7, hi7, lo8, hi8;
    upk2(P0, lo0, hi0); upk2(P1, lo1, hi1); upk2(P2, lo2, hi2);
    upk2(P3, lo3, hi3); upk2(P4, lo4, hi4); upk2(P5, lo5, hi5);
    upk2(P6, lo6, hi6); upk2(P7, lo7, hi7); upk2(P8, lo8, hi8);

    // packed odd taps (j=1..13 odd -> coeffs KC1,KC3,KC5,KC7 via symmetry)
    ull s1 = add2(P1, P7);
    ull s2 = add2(P2, P6);
    ull s3 = add2(P3, P5);
    ull c1 = ffma2(k2[3], s2, mul2(k2[1], s1));
    ull c2 = ffma2(k2[5], s3, mul2(k2[7], P4));
    ull hod = add2(c1, c2);

    // scalar even taps (j=0..14 even -> KC0,KC2,KC4,KC6) with immediates
    float t0 = hi0 + hi7, t1 = hi1 + hi6, t2 = hi2 + hi5, t3 = hi3 + hi4;
    float e0 = fmaf(t1, KC2, t0 * KC0) + fmaf(t3, KC6, t2 * KC4);
    float u0 = lo1 + lo8, u1 = lo2 + lo7, u2 = lo3 + lo6, u3 = lo4 + lo5;
    float e1 = fmaf(u1, KC2, u0 * KC0) + fmaf(u3, KC6, u2 * KC4);

    ull h = add2(hod, pk2(e0, e1));

    // vertical: row r feeds outputs t = r-d, d = 0..DMAX, coeff KC[min(d,14-d)]
#pragma unroll
    for (int d = 0; d <= DMAX; d++) {
        const int s = ((AMOD - d) % 15 + 15) % 15;
        const int ci = (d < 8) ? d : 14 - d;
        acc[s] = ffma2(k2[ci], h, acc[s]);
    }
    if (EMIT) {
        constexpr int st = (AMOD + 1) % 15;     // slot of output row r-14
        float o0, o1; upk2(acc[st], o0, o1);
        *(float2*)op = make_float2(o0, o1);
        acc[st] = 0ull;
    }
}

// Async prefetch of up to 10 rows [base, base+10) into ring slots
// sbase..sbase+9. Warp w handles rows w, w+4, ... (division-free). Commits.
__device__ __forceinline__ void prefetch10(uint32_t ring_s, float* ring_g,
                                           const float* in, int x0, int y0,
                                           int base, int sbase,
                                           bool xb, int tid) {
    if (base < NROWS) {
        int nr = NROWS - base; if (nr > 10) nr = 10;
        const int wrp = tid >> 5, lane = tid & 31;
        if (!xb) {
#pragma unroll 1
            for (int rr = wrp; rr < nr; rr += 4) {
                int gy = reflect_idx(y0 - HALO + base + rr, IMG_H);
                const float* src = in + (size_t)gy * IMG_W + (x0 - 8);
                uint32_t dst = ring_s + (uint32_t)((sbase + rr) * ROW_F * 4);
                cp16(dst + lane * 16,        src + lane * 4);
                cp16(dst + (lane + 32) * 16, src + (lane + 32) * 4);
                if (lane < 4)
                    cp16(dst + (lane + 64) * 16, src + (lane + 64) * 4);
            }
        } else {
#pragma unroll 1
            for (int rr = wrp; rr < nr; rr += 4) {
                int gy = reflect_idx(y0 - HALO + base + rr, IMG_H);
                const float* row = in + (size_t)gy * IMG_W;
                float* dst = ring_g + (sbase + rr) * ROW_F;
                for (int i = lane; i < ROW_F; i += 32)
                    dst[i] = __ldg(row + reflect_idx(x0 - 8 + i, IMG_W));
            }
        }
    }
    CP_COMMIT();
}

extern __shared__ float ring[];

__global__ void __launch_bounds__(TPB, 8)
gauss_kernel(const float* __restrict__ in, float* __restrict__ out) {
    const int tid = threadIdx.x;
    const int x0 = blockIdx.x * TILE_W;
    const int y0 = blockIdx.y * TILE_H;
    const bool xb = (blockIdx.x == 0) || (blockIdx.x == gridDim.x - 1);
    const uint32_t ring_s = (uint32_t)__cvta_generic_to_shared(ring);
    const ull* wb = (const ull*)ring + tid;          // thread's first tap pair

    // 8 packed coefficient registers, built from immediates (remat-friendly).
    ull k2[8];
    k2[0] = pk2(KC0, KC0); k2[1] = pk2(KC1, KC1);
    k2[2] = pk2(KC2, KC2); k2[3] = pk2(KC3, KC3);
    k2[4] = pk2(KC4, KC4); k2[5] = pk2(KC5, KC5);
    k2[6] = pk2(KC6, KC6); k2[7] = pk2(KC7, KC7);

    ull acc[15];
#pragma unroll
    for (int i = 0; i < 15; i++) acc[i] = 0ull;

    float* outx = out + (size_t)y0 * IMG_W + x0 + 2 * tid;
    const size_t W = IMG_W;

    // Prime: g0 (rows 0-9 -> slots 0-9), g1 (rows 10-19 -> slots 10-19).
    prefetch10(ring_s, ring, in, x0, y0,  0,  0, xb, tid);
    prefetch10(ring_s, ring, in, x0, y0, 10, 10, xb, tid);

    // Block b: wait g_b done; sync; compute its 10 rows; sync (slots of g_b
    // now reusable); prefetch g_{b+2} into the same slot half; commit.
#define BTOP() CP_WAIT(1); __syncthreads();
#define BEND(BASE, SB) __syncthreads(); \
    prefetch10(ring_s, ring, in, x0, y0, (BASE), (SB), xb, tid);

    // Steady 10-row phases (slot base SB; amod sequences 0.., 10.., 5..)
#define PH_AM0(SB, ob) \
    rstep<(SB)+0, 0,14,true>(wb, acc, k2, (ob) + 0*W); \
    rstep<(SB)+1, 1,14,true>(wb, acc, k2, (ob) + 1*W); \
    rstep<(SB)+2, 2,14,true>(wb, acc, k2, (ob) + 2*W); \
    rstep<(SB)+3, 3,14,true>(wb, acc, k2, (ob) + 3*W); \
    rstep<(SB)+4, 4,14,true>(wb, acc, k2, (ob) + 4*W); \
    rstep<(SB)+5, 5,14,true>(wb, acc, k2, (ob) + 5*W); \
    rstep<(SB)+6, 6,14,true>(wb, acc, k2, (ob) + 6*W); \
    rstep<(SB)+7, 7,14,true>(wb, acc, k2, (ob) + 7*W); \
    rstep<(SB)+8, 8,14,true>(wb, acc, k2, (ob) + 8*W); \
    rstep<(SB)+9, 9,14,true>(wb, acc, k2, (ob) + 9*W);

#define PH_AM10(SB, ob) \
    rstep<(SB)+0,10,14,true>(wb, acc, k2, (ob) + 0*W); \
    rstep<(SB)+1,11,14,true>(wb, acc, k2, (ob) + 1*W); \
    rstep<(SB)+2,12,14,true>(wb, acc, k2, (ob) + 2*W); \
    rstep<(SB)+3,13,14,true>(wb, acc, k2, (ob) + 3*W); \
    rstep<(SB)+4,14,14,true>(wb, acc, k2, (ob) + 4*W); \
    rstep<(SB)+5, 0,14,true>(wb, acc, k2, (ob) + 5*W); \
    rstep<(SB)+6, 1,14,true>(wb, acc, k2, (ob) + 6*W); \
    rstep<(SB)+7, 2,14,true>(wb, acc, k2, (ob) + 7*W); \
    rstep<(SB)+8, 3,14,true>(wb, acc, k2, (ob) + 8*W); \
    rstep<(SB)+9, 4,14,true>(wb, acc, k2, (ob) + 9*W);

#define PH_AM5(SB, ob) \
    rstep<(SB)+0, 5,14,true>(wb, acc, k2, (ob) + 0*W); \
    rstep<(SB)+1, 6,14,true>(wb, acc, k2, (ob) + 1*W); \
    rstep<(SB)+2, 7,14,true>(wb, acc, k2, (ob) + 2*W); \
    rstep<(SB)+3, 8,14,true>(wb, acc, k2, (ob) + 3*W); \
    rstep<(SB)+4, 9,14,true>(wb, acc, k2, (ob) + 4*W); \
    rstep<(SB)+5,10,14,true>(wb, acc, k2, (ob) + 5*W); \
    rstep<(SB)+6,11,14,true>(wb, acc, k2, (ob) + 6*W); \
    rstep<(SB)+7,12,14,true>(wb, acc, k2, (ob) + 7*W); \
    rstep<(SB)+8,13,14,true>(wb, acc, k2, (ob) + 8*W); \
    rstep<(SB)+9,14,14,true>(wb, acc, k2, (ob) + 9*W);

    // ---- B0: rows 0..9 (warmup) ----
    BTOP()
    rstep<0,0,0,false>(wb, acc, k2, outx);
    rstep<1,1,1,false>(wb, acc, k2, outx);
    rstep<2,2,2,false>(wb, acc, k2, outx);
    rstep<3,3,3,false>(wb, acc, k2, outx);
    rstep<4,4,4,false>(wb, acc, k2, outx);
    rstep<5,5,5,false>(wb, acc, k2, outx);
    rstep<6,6,6,false>(wb, acc, k2, outx);
    rstep<7,7,7,false>(wb, acc, k2, outx);
    rstep<8,8,8,false>(wb, acc, k2, outx);
    rstep<9,9,9,false>(wb, acc, k2, outx);
    BEND(20, 0)                                     // g2: rows 20-29 -> slots 0-9

    // ---- B1: rows 10..19 (rows 14..19 emit outputs 0..5) ----
    BTOP()
    rstep<10,10,10,false>(wb, acc, k2, outx);
    rstep<11,11,11,false>(wb, acc, k2, outx);
    rstep<12,12,12,false>(wb, acc, k2, outx);
    rstep<13,13,13,false>(wb, acc, k2, outx);
    rstep<14,14,14,true >(wb, acc, k2, outx + 0*W);
    rstep<15, 0,14,true >(wb, acc, k2, outx + 1*W);
    rstep<16, 1,14,true >(wb, acc, k2, outx + 2*W);
    rstep<17, 2,14,true >(wb, acc, k2, outx + 3*W);
    rstep<18, 3,14,true >(wb, acc, k2, outx + 4*W);
    rstep<19, 4,14,true >(wb, acc, k2, outx + 5*W);
    BEND(30, 10)                                    // g3: rows 30-39 -> slots 10-19

    // ---- B2: rows 20..29 -> outputs 6..15 ----
    BTOP()
    PH_AM5(0, outx + (size_t)6 * W)
    BEND(40, 0)                                     // g4
    // ---- B3: rows 30..39 -> outputs 16..25 ----
    BTOP()
    PH_AM0(10, outx + (size_t)16 * W)
    BEND(50, 10)                                    // g5
    // ---- B4: rows 40..49 -> outputs 26..35 ----
    BTOP()
    PH_AM10(0, outx + (size_t)26 * W)
    BEND(60, 0)                                     // g6
    // ---- B5: rows 50..59 -> outputs 36..45 ----
    BTOP()
    PH_AM5(10, outx + (size_t)36 * W)
    BEND(70, 10)                                    // g7: rows 70-77 -> slots 10-17
    // ---- B6: rows 60..69 -> outputs 46..55 ----
    BTOP()
    PH_AM0(0, outx + (size_t)46 * W)
    BEND(80, 0)                                     // g8: empty commit
    // ---- B7: rows 70..77 -> outputs 56..63 ----
    BTOP()
    {
        float* ob = outx + (size_t)56 * W;
        rstep<10,10,14,true>(wb, acc, k2, ob + 0*W);
        rstep<11,11,14,true>(wb, acc, k2, ob + 1*W);
        rstep<12,12,14,true>(wb, acc, k2, ob + 2*W);
        rstep<13,13,14,true>(wb, acc, k2, ob + 3*W);
        rstep<14,14,14,true>(wb, acc, k2, ob + 4*W);
        rstep<15, 0,14,true>(wb, acc, k2, ob + 5*W);
        rstep<16, 1,14,true>(wb, acc, k2, ob + 6*W);
        rstep<17, 2,14,true>(wb, acc, k2, ob + 7*W);
    }
}

extern "C" void kernel_launch(void* const* d_in, const int* in_sizes, int n_in,
                              void* d_out, int out_size) {
    const float* img = (const float*)d_in[0];   // [8192,8192] f32
    float* out = (float*)d_out;                 // [8192,8192] f32
    (void)in_sizes; (void)n_in; (void)out_size;

    dim3 grid(IMG_W / TILE_W, IMG_H / TILE_H);  // 32 x 128
    gauss_kernel<<<grid, TPB, SMEM_BYTES>>>(img, out);
}